// round 7
// baseline (speedup 1.0000x reference)
#include <cuda_runtime.h>
#include <cstdint>
#include <cstddef>

#define NN   8192
#define FIN  256
#define FOUT 128
#define MT   64
#define JT   128
#define SPS  132
#define SBS  136
#define NTL  64

__device__ float g_Wh [NN * FOUT];
__device__ float g_Whr[NN * FOUT];   // tf32-rounded, row-major (MMA B source)
__device__ float g_ss[NN], g_us[NN], g_u5[NN];
__device__ float g_sd[NN], g_vd[NN], g_v5[NN];

__device__ __forceinline__ float to_tf32(float x) {
    unsigned r; asm("cvt.rna.tf32.f32 %0, %1;" : "=r"(r) : "f"(x));
    return __uint_as_float(r);
}

#define CPASYNC16(dst, src) \
    asm volatile("cp.async.cg.shared.global [%0], [%1], 16;" :: "r"(dst), "l"(src))
#define CPCOMMIT() asm volatile("cp.async.commit_group;" ::: "memory")
#define CPWAIT0()  asm volatile("cp.async.wait_group 0;" ::: "memory")
#define BAR_SYNC(id)   asm volatile("bar.sync %0, 256;"   :: "r"(id) : "memory")
#define BAR_ARRIVE(id) asm volatile("bar.arrive %0, 256;" :: "r"(id) : "memory")
#define MMA8(d, a0, a1, a2, a3, b0, b1) \
    asm volatile("mma.sync.aligned.m16n8k8.row.col.f32.tf32.tf32.f32 " \
                 "{%0,%1,%2,%3}, {%4,%5,%6,%7}, {%8,%9}, {%0,%1,%2,%3};\n" \
                 : "+f"(d[0]), "+f"(d[1]), "+f"(d[2]), "+f"(d[3]) \
                 : "r"(a0), "r"(a1), "r"(a2), "r"(a3), "r"(b0), "r"(b1))

// barrier ids: FULL(s)=1+s, EMPTY(s)=3+s
#define FULLB(s)  (1 + (s))
#define EMPTYB(s) (3 + (s))

// ---------------- Phase 1: Wh = h @ W^T ----------------
__global__ void __launch_bounds__(256) k_wh(const float* __restrict__ h,
                                            const float* __restrict__ W) {
    __shared__ float sH[32][68];
    __shared__ float sW[32][132];
    const int t = threadIdx.x, i0 = blockIdx.x * 64;
    const int rb = (t >> 5) * 8, cb = (t & 31) * 4;
    float acc[8][4];
#pragma unroll
    for (int r = 0; r < 8; r++)
#pragma unroll
        for (int c = 0; c < 4; c++) acc[r][c] = 0.f;
    for (int k0 = 0; k0 < FIN; k0 += 32) {
        __syncthreads();
#pragma unroll
        for (int it = 0; it < 2; it++) {
            int idx = t + 256 * it, row = idx >> 3, kc = (idx & 7) * 4;
            float4 v = *reinterpret_cast<const float4*>(h + (size_t)(i0 + row) * FIN + k0 + kc);
            sH[kc][row] = v.x; sH[kc + 1][row] = v.y; sH[kc + 2][row] = v.z; sH[kc + 3][row] = v.w;
        }
#pragma unroll
        for (int it = 0; it < 4; it++) {
            int idx = t + 256 * it, f = idx >> 3, kc = (idx & 7) * 4;
            float4 v = *reinterpret_cast<const float4*>(W + (size_t)f * FIN + k0 + kc);
            sW[kc][f] = v.x; sW[kc + 1][f] = v.y; sW[kc + 2][f] = v.z; sW[kc + 3][f] = v.w;
        }
        __syncthreads();
#pragma unroll
        for (int k = 0; k < 32; k++) {
            float a[8], b[4];
            *reinterpret_cast<float4*>(a)     = *reinterpret_cast<const float4*>(&sH[k][rb]);
            *reinterpret_cast<float4*>(a + 4) = *reinterpret_cast<const float4*>(&sH[k][rb + 4]);
            *reinterpret_cast<float4*>(b)     = *reinterpret_cast<const float4*>(&sW[k][cb]);
#pragma unroll
            for (int r = 0; r < 8; r++)
#pragma unroll
                for (int c = 0; c < 4; c++) acc[r][c] = fmaf(a[r], b[c], acc[r][c]);
        }
    }
#pragma unroll
    for (int r = 0; r < 8; r++) {
        float4 v  = make_float4(acc[r][0], acc[r][1], acc[r][2], acc[r][3]);
        float4 vr = make_float4(to_tf32(v.x), to_tf32(v.y), to_tf32(v.z), to_tf32(v.w));
        *reinterpret_cast<float4*>(g_Wh  + (size_t)(i0 + rb + r) * FOUT + cb) = v;
        *reinterpret_cast<float4*>(g_Whr + (size_t)(i0 + rb + r) * FOUT + cb) = vr;
    }
}

// ---------------- Phase 2: scores + exp factors ----------------
__global__ void __launch_bounds__(256) k_score(const float* __restrict__ a_vec) {
    int gw = (blockIdx.x * blockDim.x + threadIdx.x) >> 5, lane = threadIdx.x & 31;
    if (gw >= NN) return;
    float4 w  = reinterpret_cast<const float4*>(g_Wh + (size_t)gw * FOUT)[lane];
    float4 as = reinterpret_cast<const float4*>(a_vec)[lane];
    float4 ad = reinterpret_cast<const float4*>(a_vec + FOUT)[lane];
    float ss = w.x * as.x + w.y * as.y + w.z * as.z + w.w * as.w;
    float sd = w.x * ad.x + w.y * ad.y + w.z * ad.z + w.w * ad.w;
#pragma unroll
    for (int o = 16; o > 0; o >>= 1) {
        ss += __shfl_xor_sync(0xffffffffu, ss, o);
        sd += __shfl_xor_sync(0xffffffffu, sd, o);
    }
    if (lane == 0) {
        g_ss[gw] = ss; g_us[gw] = expf(ss); g_u5[gw] = expf(0.2f * ss);
        g_sd[gw] = sd; g_vd[gw] = expf(sd); g_v5[gw] = expf(0.2f * sd);
    }
}

// ------- Phase 3: warp-specialized fused masked-softmax @ Wh -------
extern __shared__ float dynsmem[];

__global__ void __launch_bounds__(256, 1) k_gat(const int* __restrict__ adj,
                                                float* __restrict__ out) {
    float* sP[2];
    float* sB[2];
    sP[0] = dynsmem;
    sP[1] = sP[0] + MT * SPS;
    sB[0] = sP[1] + MT * SPS;
    sB[1] = sB[0] + JT * SBS;
    float* sDen = sB[1] + JT * SBS;

    const int t    = threadIdx.x;
    const int lane = t & 31;
    const int w    = t >> 5;
    const int i0   = blockIdx.x * MT;

    const uint32_t sBu[2] = {(uint32_t)__cvta_generic_to_shared(sB[0]),
                             (uint32_t)__cvta_generic_to_shared(sB[1])};

    if (w < 4) {
        // ================= PRODUCER (warps 0-3) =================
        const int p     = t;          // 0..127
        const int row   = p >> 1;     // 0..63
        const int half  = p & 1;
        const int jbase = half * 64;

        const float ssv = g_ss[i0 + row];
        const float usv = g_us[i0 + row];
        const float u5v = g_u5[i0 + row];
        float den = 0.f;

        // prefetch adj for tile 0
        int4 am[16];
        {
            const int* ar = adj + (size_t)(i0 + row) * NN + jbase;
#pragma unroll
            for (int q = 0; q < 16; q++)
                am[q] = *reinterpret_cast<const int4*>(ar + q * 4);
        }

        for (int jt = 0; jt < NTL; jt++) {
            const int s = jt & 1;
            if (jt >= 2) BAR_SYNC(EMPTYB(s));

            // stage B(jt) via cp.async (32 x 16B per thread)
            {
                const float* bsrc = g_Whr + (size_t)jt * JT * FOUT;
                const uint32_t d = sBu[s];
#pragma unroll
                for (int i = 0; i < 32; i++) {
                    int c = p + 128 * i, r = c >> 5, q = c & 31;
                    CPASYNC16(d + (uint32_t)(r * SBS + q * 4) * 4u,
                              bsrc + (size_t)r * FOUT + q * 4);
                }
                CPCOMMIT();
            }

            // P-gen(jt): this thread covers row, cols jbase..jbase+63
            {
                const int j0 = jt * JT + jbase;
                const float* sdp = g_sd + j0;
                const float* vdp = g_vd + j0;
                const float* v5p = g_v5 + j0;
                float* dst = sP[s] + row * SPS + jbase;
#pragma unroll
                for (int q = 0; q < 16; q++) {
                    float4 sd4 = *reinterpret_cast<const float4*>(sdp + q * 4);
                    float4 vd4 = *reinterpret_cast<const float4*>(vdp + q * 4);
                    float4 v54 = *reinterpret_cast<const float4*>(v5p + q * 4);
                    float p0 = (ssv + sd4.x) > 0.f ? usv * vd4.x : u5v * v54.x;
                    float p1 = (ssv + sd4.y) > 0.f ? usv * vd4.y : u5v * v54.y;
                    float p2 = (ssv + sd4.z) > 0.f ? usv * vd4.z : u5v * v54.z;
                    float p3 = (ssv + sd4.w) > 0.f ? usv * vd4.w : u5v * v54.w;
                    p0 = am[q].x > 0 ? p0 : 0.f;
                    p1 = am[q].y > 0 ? p1 : 0.f;
                    p2 = am[q].z > 0 ? p2 : 0.f;
                    p3 = am[q].w > 0 ? p3 : 0.f;
                    den += (p0 + p1) + (p2 + p3);
                    *reinterpret_cast<float4*>(dst + q * 4) =
                        make_float4(to_tf32(p0), to_tf32(p1), to_tf32(p2), to_tf32(p3));
                }
            }

            // prefetch adj for tile jt+1
            if (jt + 1 < NTL) {
                const int* ar = adj + (size_t)(i0 + row) * NN + (jt + 1) * JT + jbase;
#pragma unroll
                for (int q = 0; q < 16; q++)
                    am[q] = *reinterpret_cast<const int4*>(ar + q * 4);
            }

            CPWAIT0();             // B(jt) resident
            BAR_ARRIVE(FULLB(s));  // hand buffer s to consumers
        }

        // denominator: combine the two column-halves of each row
        den += __shfl_xor_sync(0xffffffffu, den, 1);
        if (half == 0) sDen[row] = den;
    } else {
        // ================= CONSUMER (warps 4-7) =================
        const int cw   = w - 4;          // 0..3
        const int ncol = cw * 32;
        const int qr   = lane >> 2;
        const int qc   = lane & 3;

        float acc[4][4][4];
#pragma unroll
        for (int mb = 0; mb < 4; mb++)
#pragma unroll
            for (int nb = 0; nb < 4; nb++)
#pragma unroll
                for (int c = 0; c < 4; c++) acc[mb][nb][c] = 0.f;

        for (int jt = 0; jt < NTL; jt++) {
            const int s = jt & 1;
            BAR_SYNC(FULLB(s));
            const float* sPb = sP[s];
            const float* sBb = sB[s];
#pragma unroll
            for (int ks = 0; ks < 16; ks++) {
                const int kk = ks * 8;
                unsigned a[4][4];
#pragma unroll
                for (int mb = 0; mb < 4; mb++) {
                    const int ar = mb * 16 + qr;
                    a[mb][0] = __float_as_uint(sPb[ar * SPS + kk + qc]);
                    a[mb][1] = __float_as_uint(sPb[(ar + 8) * SPS + kk + qc]);
                    a[mb][2] = __float_as_uint(sPb[ar * SPS + kk + qc + 4]);
                    a[mb][3] = __float_as_uint(sPb[(ar + 8) * SPS + kk + qc + 4]);
                }
#pragma unroll
                for (int nb = 0; nb < 4; nb++) {
                    const int bc = ncol + nb * 8 + qr;
                    unsigned b0 = __float_as_uint(sBb[(kk + qc) * SBS + bc]);
                    unsigned b1 = __float_as_uint(sBb[(kk + qc + 4) * SBS + bc]);
#pragma unroll
                    for (int mb = 0; mb < 4; mb++)
                        MMA8(acc[mb][nb], a[mb][0], a[mb][1], a[mb][2], a[mb][3], b0, b1);
                }
            }
            BAR_ARRIVE(EMPTYB(s));
        }

        __syncthreads();   // producers' sDen visible

        // epilogue: scale by 1/den, store
#pragma unroll
        for (int mb = 0; mb < 4; mb++) {
            const int rbase = mb * 16 + qr;
            const float rd0 = 1.f / sDen[rbase];
            const float rd1 = 1.f / sDen[rbase + 8];
            const int r0 = i0 + rbase;
#pragma unroll
            for (int nb = 0; nb < 4; nb++) {
                int col = ncol + nb * 8 + qc * 2;
                *reinterpret_cast<float2*>(out + (size_t)r0 * FOUT + col) =
                    make_float2(acc[mb][nb][0] * rd0, acc[mb][nb][1] * rd0);
                *reinterpret_cast<float2*>(out + (size_t)(r0 + 8) * FOUT + col) =
                    make_float2(acc[mb][nb][2] * rd1, acc[mb][nb][3] * rd1);
            }
        }
        return;
    }
    __syncthreads();   // producer side of the final barrier
}

// ---------------------------------------------------------------
extern "C" void kernel_launch(void* const* d_in, const int* in_sizes, int n_in,
                              void* d_out, int out_size) {
    const float* h   = (const float*)d_in[0];
    const int*   adj = (const int*)d_in[1];
    const float* W   = (const float*)d_in[2];
    const float* a   = (const float*)d_in[3];
    float*       out = (float*)d_out;
    (void)in_sizes; (void)n_in; (void)out_size;

    const int smem_bytes = (2 * MT * SPS + 2 * JT * SBS + MT) * (int)sizeof(float);
    static int inited = 0;
    if (!inited) {
        cudaFuncSetAttribute(k_gat, cudaFuncAttributeMaxDynamicSharedMemorySize, smem_bytes);
        inited = 1;
    }
    k_wh<<<NN / 64, 256>>>(h, W);
    k_score<<<NN / 8, 256>>>(a);
    k_gat<<<NN / MT, 256, smem_bytes>>>(adj, out);
}

// round 8
// speedup vs baseline: 1.3109x; 1.3109x over previous
#include <cuda_runtime.h>
#include <cuda_fp16.h>
#include <cstdint>
#include <cstddef>

#define NN   8192
#define FIN  256
#define FOUT 128
#define MT   64
#define JT   128
#define NTL  64

__device__ float  g_Wh[NN * FOUT];      // fp32 Wh (scores)
__device__ __half g_WhT[FOUT * NN];     // fp16 Wh^T, n-major (MMA B source)
__device__ float  g_ss[NN], g_sd[NN];
__device__ float  g_us[NN], g_u5[NN];   // scaled row exp factors
__device__ float  g_vd[NN], g_v5[NN];   // col exp factors
__device__ float  g_M;

#define CPASYNC16(dst, src) \
    asm volatile("cp.async.cg.shared.global [%0], [%1], 16;" :: "r"(dst), "l"(src))
#define CPCOMMIT() asm volatile("cp.async.commit_group;" ::: "memory")
#define CPWAIT1()  asm volatile("cp.async.wait_group 1;" ::: "memory")
#define LDSM4(r0, r1, r2, r3, addr) \
    asm volatile("ldmatrix.sync.aligned.m8n8.x4.shared.b16 {%0,%1,%2,%3}, [%4];" \
                 : "=r"(r0), "=r"(r1), "=r"(r2), "=r"(r3) : "r"(addr))
#define MMA16(d, a0, a1, a2, a3, b0, b1) \
    asm volatile("mma.sync.aligned.m16n8k16.row.col.f32.f16.f16.f32 " \
                 "{%0,%1,%2,%3}, {%4,%5,%6,%7}, {%8,%9}, {%0,%1,%2,%3};\n" \
                 : "+f"(d[0]), "+f"(d[1]), "+f"(d[2]), "+f"(d[3]) \
                 : "r"(a0), "r"(a1), "r"(a2), "r"(a3), "r"(b0), "r"(b1))

__device__ __forceinline__ unsigned packh2(float a, float b) {
    __half2 h = __floats2half2_rn(a, b);
    return *reinterpret_cast<unsigned*>(&h);
}

// ---------------- Phase 1: Wh = h @ W^T (+ fp16 Wh^T) ----------------
__global__ void __launch_bounds__(256) k_wh(const float* __restrict__ h,
                                            const float* __restrict__ W) {
    __shared__ float sH[32][68];
    __shared__ float sW[32][132];
    const int t = threadIdx.x, i0 = blockIdx.x * 64;
    const int rb = (t >> 5) * 8, cb = (t & 31) * 4;
    float acc[8][4];
#pragma unroll
    for (int r = 0; r < 8; r++)
#pragma unroll
        for (int c = 0; c < 4; c++) acc[r][c] = 0.f;
    for (int k0 = 0; k0 < FIN; k0 += 32) {
        __syncthreads();
#pragma unroll
        for (int it = 0; it < 2; it++) {
            int idx = t + 256 * it, row = idx >> 3, kc = (idx & 7) * 4;
            float4 v = *reinterpret_cast<const float4*>(h + (size_t)(i0 + row) * FIN + k0 + kc);
            sH[kc][row] = v.x; sH[kc + 1][row] = v.y; sH[kc + 2][row] = v.z; sH[kc + 3][row] = v.w;
        }
#pragma unroll
        for (int it = 0; it < 4; it++) {
            int idx = t + 256 * it, f = idx >> 3, kc = (idx & 7) * 4;
            float4 v = *reinterpret_cast<const float4*>(W + (size_t)f * FIN + k0 + kc);
            sW[kc][f] = v.x; sW[kc + 1][f] = v.y; sW[kc + 2][f] = v.z; sW[kc + 3][f] = v.w;
        }
        __syncthreads();
#pragma unroll
        for (int k = 0; k < 32; k++) {
            float a[8], b[4];
            *reinterpret_cast<float4*>(a)     = *reinterpret_cast<const float4*>(&sH[k][rb]);
            *reinterpret_cast<float4*>(a + 4) = *reinterpret_cast<const float4*>(&sH[k][rb + 4]);
            *reinterpret_cast<float4*>(b)     = *reinterpret_cast<const float4*>(&sW[k][cb]);
#pragma unroll
            for (int r = 0; r < 8; r++)
#pragma unroll
                for (int c = 0; c < 4; c++) acc[r][c] = fmaf(a[r], b[c], acc[r][c]);
        }
    }
#pragma unroll
    for (int r = 0; r < 8; r++)
        *reinterpret_cast<float4*>(g_Wh + (size_t)(i0 + rb + r) * FOUT + cb) =
            make_float4(acc[r][0], acc[r][1], acc[r][2], acc[r][3]);
    // fp16 transposed copy: g_WhT[n][i], 8 consecutive i per uint4
#pragma unroll
    for (int c = 0; c < 4; c++) {
        uint4 v;
        v.x = packh2(acc[0][c], acc[1][c]);
        v.y = packh2(acc[2][c], acc[3][c]);
        v.z = packh2(acc[4][c], acc[5][c]);
        v.w = packh2(acc[6][c], acc[7][c]);
        *reinterpret_cast<uint4*>(g_WhT + (size_t)(cb + c) * NN + i0 + rb) = v;
    }
}

// ---------------- Phase 2: raw scores ----------------
__global__ void __launch_bounds__(256) k_score(const float* __restrict__ a_vec) {
    int gw = (blockIdx.x * blockDim.x + threadIdx.x) >> 5, lane = threadIdx.x & 31;
    if (gw >= NN) return;
    float4 w  = reinterpret_cast<const float4*>(g_Wh + (size_t)gw * FOUT)[lane];
    float4 as = reinterpret_cast<const float4*>(a_vec)[lane];
    float4 ad = reinterpret_cast<const float4*>(a_vec + FOUT)[lane];
    float ss = w.x * as.x + w.y * as.y + w.z * as.z + w.w * as.w;
    float sd = w.x * ad.x + w.y * ad.y + w.z * ad.z + w.w * ad.w;
#pragma unroll
    for (int o = 16; o > 0; o >>= 1) {
        ss += __shfl_xor_sync(0xffffffffu, ss, o);
        sd += __shfl_xor_sync(0xffffffffu, sd, o);
    }
    if (lane == 0) { g_ss[gw] = ss; g_sd[gw] = sd; }
}

// ---------------- Phase 2b: max(sd), then exp factors ----------------
__global__ void __launch_bounds__(256) k_max() {
    __shared__ float sm[8];
    const int t = threadIdx.x;
    float m = -1e30f;
    for (int i = t; i < NN; i += 256) m = fmaxf(m, g_sd[i]);
#pragma unroll
    for (int o = 16; o > 0; o >>= 1) m = fmaxf(m, __shfl_xor_sync(0xffffffffu, m, o));
    if ((t & 31) == 0) sm[t >> 5] = m;
    __syncthreads();
    if (t == 0) {
        float r = sm[0];
#pragma unroll
        for (int i = 1; i < 8; i++) r = fmaxf(r, sm[i]);
        g_M = r;
    }
}

__global__ void __launch_bounds__(256) k_prep() {
    int i = blockIdx.x * 256 + threadIdx.x;
    float M = g_M;
    float ss = g_ss[i], sd = g_sd[i];
    float x = ss + M;
    float LRm = x > 0.f ? x : 0.2f * x;      // exact upper bound of LR(ss+sd_j)
    g_us[i] = expf(ss - LRm);
    g_u5[i] = expf(fmaf(0.2f, ss, -LRm));
    g_vd[i] = expf(sd);
    g_v5[i] = expf(0.2f * sd);
}

// ------- Phase 3: fused masked-softmax @ Wh (fp16 ldmatrix + mma) -------
extern __shared__ float dynsmem[];

__global__ void __launch_bounds__(256, 1) k_gat(const int* __restrict__ adj,
                                                float* __restrict__ out) {
    // sA: 64 rows x 256B (fp16, swizzled)   = 16 KB
    // sB: 2 x (128 rows x 256B)             = 64 KB
    // sDen: 64 floats
    char* sAc = reinterpret_cast<char*>(dynsmem);
    char* sBc = sAc + 16384;
    float* sDen = reinterpret_cast<float*>(sBc + 2 * 32768);
    const uint32_t sAu = (uint32_t)__cvta_generic_to_shared(sAc);
    const uint32_t sBu0 = (uint32_t)__cvta_generic_to_shared(sBc);

    const int t    = threadIdx.x;
    const int lane = t & 31;
    const int w    = t >> 5;
    const int i0   = blockIdx.x * MT;

    // ---- P-gen mapping: thread -> (row, 32-col quarter) ----
    const int prow = t >> 2;
    const int pq   = t & 3;
    const float ssv = g_ss[i0 + prow];
    const float usv = g_us[i0 + prow];
    const float u5v = g_u5[i0 + prow];
    const int   prx = prow & 7;
    const uint32_t pBase = sAu + (uint32_t)prow * 256u;
    float den = 0.f;

    // ---- MMA mapping: warp grid 2 (rows) x 4 (cols), 32x32 tiles ----
    const int mrow = (w & 1) * 32;
    const int ncol = (w >> 1) * 32;
    uint32_t aOff[2]; int aRx[2];
#pragma unroll
    for (int mb = 0; mb < 2; mb++) {
        int r = mrow + mb * 16 + (lane & 7) + 8 * ((lane >> 3) & 1);
        aOff[mb] = (uint32_t)r * 256u;
        aRx[mb] = r & 7;
    }
    const int aCb = lane >> 4;
    const int bn  = ncol + (lane & 7) + 8 * (lane >> 4);
    const uint32_t bOff = (uint32_t)bn * 256u;
    const int bRx = bn & 7;
    const int bCb = (lane >> 3) & 1;

    float acc[2][4][4];
#pragma unroll
    for (int mb = 0; mb < 2; mb++)
#pragma unroll
        for (int nb = 0; nb < 4; nb++)
#pragma unroll
            for (int c = 0; c < 4; c++) acc[mb][nb][c] = 0.f;

    // ---- prologue: B(0) cp.async + adj(0) prefetch ----
    const int* arow = adj + (size_t)(i0 + prow) * NN + pq * 32;
#pragma unroll
    for (int i = 0; i < 8; i++) {
        int g = t + 256 * i, r = g >> 4, c = g & 15;
        CPASYNC16(sBu0 + (uint32_t)r * 256u + (uint32_t)((c ^ (r & 7)) << 4),
                  g_WhT + (size_t)r * NN + c * 8);
    }
    CPCOMMIT();
    int4 am[8];
#pragma unroll
    for (int q = 0; q < 8; q++)
        am[q] = *reinterpret_cast<const int4*>(arow + q * 4);

#pragma unroll 1
    for (int jt = 0; jt < NTL; jt++) {
        const int s = jt & 1;
        const uint32_t sBs = sBu0 + (uint32_t)s * 32768u;

        // ---- P-gen(jt) -> sA (fp16, swizzled) ----
        {
            const int j0 = jt * JT + pq * 32;
            unsigned hh[16];
#pragma unroll
            for (int q = 0; q < 8; q++) {
                float4 sd4 = *reinterpret_cast<const float4*>(g_sd + j0 + q * 4);
                float4 vd4 = *reinterpret_cast<const float4*>(g_vd + j0 + q * 4);
                float4 v54 = *reinterpret_cast<const float4*>(g_v5 + j0 + q * 4);
                float p0 = (ssv + sd4.x) > 0.f ? usv * vd4.x : u5v * v54.x;
                float p1 = (ssv + sd4.y) > 0.f ? usv * vd4.y : u5v * v54.y;
                float p2 = (ssv + sd4.z) > 0.f ? usv * vd4.z : u5v * v54.z;
                float p3 = (ssv + sd4.w) > 0.f ? usv * vd4.w : u5v * v54.w;
                p0 = am[q].x > 0 ? p0 : 0.f;
                p1 = am[q].y > 0 ? p1 : 0.f;
                p2 = am[q].z > 0 ? p2 : 0.f;
                p3 = am[q].w > 0 ? p3 : 0.f;
                den += (p0 + p1) + (p2 + p3);
                hh[2 * q]     = packh2(p0, p1);
                hh[2 * q + 1] = packh2(p2, p3);
            }
#pragma unroll
            for (int i = 0; i < 4; i++) {
                int c = pq * 4 + i;
                uint32_t a = pBase + (uint32_t)((c ^ prx) << 4);
                asm volatile("st.shared.v4.b32 [%0], {%1,%2,%3,%4};"
                             :: "r"(a), "r"(hh[4 * i]), "r"(hh[4 * i + 1]),
                                "r"(hh[4 * i + 2]), "r"(hh[4 * i + 3]) : "memory");
            }
        }

        // ---- cp.async B(jt+1); adj prefetch(jt+1) ----
        if (jt + 1 < NTL) {
            const __half* bsrc = g_WhT + (size_t)(jt + 1) * JT;
            const uint32_t d = sBu0 + (uint32_t)(s ^ 1) * 32768u;
#pragma unroll
            for (int i = 0; i < 8; i++) {
                int g = t + 256 * i, r = g >> 4, c = g & 15;
                CPASYNC16(d + (uint32_t)r * 256u + (uint32_t)((c ^ (r & 7)) << 4),
                          bsrc + (size_t)r * NN + c * 8);
            }
        }
        CPCOMMIT();
        if (jt + 1 < NTL) {
            const int* an = arow + (size_t)(jt + 1) * JT;
#pragma unroll
            for (int q = 0; q < 8; q++)
                am[q] = *reinterpret_cast<const int4*>(an + q * 4);
        }

        CPWAIT1();          // B(jt) resident
        __syncthreads();    // sA(jt) published

        // ---- MMA(jt) ----
#pragma unroll
        for (int ks = 0; ks < 8; ks++) {
            unsigned a[2][4], bb0[4], bb1[4];
#pragma unroll
            for (int mb = 0; mb < 2; mb++) {
                uint32_t ad = sAu + aOff[mb] + (uint32_t)(((2 * ks + aCb) ^ aRx[mb]) << 4);
                LDSM4(a[mb][0], a[mb][1], a[mb][2], a[mb][3], ad);
            }
            {
                uint32_t c16 = (uint32_t)(((2 * ks + bCb) ^ bRx) << 4);
                uint32_t b0a = sBs + bOff + c16;
                uint32_t b1a = b0a + 16u * 256u;
                LDSM4(bb0[0], bb0[1], bb0[2], bb0[3], b0a);
                LDSM4(bb1[0], bb1[1], bb1[2], bb1[3], b1a);
            }
#pragma unroll
            for (int mb = 0; mb < 2; mb++) {
                MMA16(acc[mb][0], a[mb][0], a[mb][1], a[mb][2], a[mb][3], bb0[0], bb0[1]);
                MMA16(acc[mb][1], a[mb][0], a[mb][1], a[mb][2], a[mb][3], bb0[2], bb0[3]);
                MMA16(acc[mb][2], a[mb][0], a[mb][1], a[mb][2], a[mb][3], bb1[0], bb1[1]);
                MMA16(acc[mb][3], a[mb][0], a[mb][1], a[mb][2], a[mb][3], bb1[2], bb1[3]);
            }
        }
        __syncthreads();    // sA free for P-gen(jt+1)
    }

    // ---- denominators: 4 threads per row ----
    den += __shfl_xor_sync(0xffffffffu, den, 1);
    den += __shfl_xor_sync(0xffffffffu, den, 2);
    if (pq == 0) sDen[prow] = den;
    __syncthreads();

    // ---- epilogue ----
    const int qr = lane >> 2, qc = lane & 3;
#pragma unroll
    for (int mb = 0; mb < 2; mb++) {
        const int rbase = mrow + mb * 16 + qr;
        const float rd0 = 1.f / sDen[rbase];
        const float rd1 = 1.f / sDen[rbase + 8];
        const int r0 = i0 + rbase;
#pragma unroll
        for (int nb = 0; nb < 4; nb++) {
            int col = ncol + nb * 8 + qc * 2;
            *reinterpret_cast<float2*>(out + (size_t)r0 * FOUT + col) =
                make_float2(acc[mb][nb][0] * rd0, acc[mb][nb][1] * rd0);
            *reinterpret_cast<float2*>(out + (size_t)(r0 + 8) * FOUT + col) =
                make_float2(acc[mb][nb][2] * rd1, acc[mb][nb][3] * rd1);
        }
    }
}

// ---------------------------------------------------------------
extern "C" void kernel_launch(void* const* d_in, const int* in_sizes, int n_in,
                              void* d_out, int out_size) {
    const float* h   = (const float*)d_in[0];
    const int*   adj = (const int*)d_in[1];
    const float* W   = (const float*)d_in[2];
    const float* a   = (const float*)d_in[3];
    float*       out = (float*)d_out;
    (void)in_sizes; (void)n_in; (void)out_size;

    const int smem_bytes = 16384 + 2 * 32768 + 256;
    static int inited = 0;
    if (!inited) {
        cudaFuncSetAttribute(k_gat, cudaFuncAttributeMaxDynamicSharedMemorySize, smem_bytes);
        inited = 1;
    }
    k_wh<<<NN / 64, 256>>>(h, W);
    k_score<<<NN / 8, 256>>>(a);
    k_max<<<1, 256>>>();
    k_prep<<<NN / 256, 256>>>();
    k_gat<<<NN / MT, 256, smem_bytes>>>(adj, out);
}

// round 9
// speedup vs baseline: 2.1983x; 1.6769x over previous
#include <cuda_runtime.h>
#include <cuda_fp16.h>
#include <cstdint>
#include <cstddef>

#define NN   8192
#define FIN  256
#define FOUT 128
#define MT   64
#define JT   128
#define NTL  64
#define SPH  136   // sA row stride in halves (136/2=68 ≡ 4 mod 32 -> conflict-free)
#define SBH  136   // sB row stride in halves

__device__ float  g_Wh[NN * FOUT];     // fp32 Wh (scores)
__device__ __half g_WhT[FOUT * NN];    // fp16 Wh^T n-major (MMA B source)
__device__ float  g_ss[NN], g_sd[NN];
__device__ float  g_us[NN], g_u5[NN];  // prescaled row exp factors
__device__ float  g_vd[NN], g_v5[NN];  // col exp factors
__device__ float  g_M;

#define CPASYNC16(dst, src) \
    asm volatile("cp.async.cg.shared.global [%0], [%1], 16;" :: "r"(dst), "l"(src))
#define CPCOMMIT() asm volatile("cp.async.commit_group;" ::: "memory")
#define CPWAIT1()  asm volatile("cp.async.wait_group 1;" ::: "memory")
#define LDS32(x, a) asm volatile("ld.shared.b32 %0, [%1];" : "=r"(x) : "r"(a))
#define STS64(a, x, y) \
    asm volatile("st.shared.v2.b32 [%0], {%1,%2};" :: "r"(a), "r"(x), "r"(y) : "memory")
#define MMA16(d, a0, a1, a2, a3, b0, b1) \
    asm volatile("mma.sync.aligned.m16n8k16.row.col.f32.f16.f16.f32 " \
                 "{%0,%1,%2,%3}, {%4,%5,%6,%7}, {%8,%9}, {%0,%1,%2,%3};\n" \
                 : "+f"(d[0]), "+f"(d[1]), "+f"(d[2]), "+f"(d[3]) \
                 : "r"(a0), "r"(a1), "r"(a2), "r"(a3), "r"(b0), "r"(b1))

__device__ __forceinline__ unsigned packh2(float a, float b) {
    __half2 h = __floats2half2_rn(a, b);
    return *reinterpret_cast<unsigned*>(&h);
}

// ---------------- Phase 1: Wh = h @ W^T (+ fp16 Wh^T) ----------------
__global__ void __launch_bounds__(256) k_wh(const float* __restrict__ h,
                                            const float* __restrict__ W) {
    __shared__ float sH[32][68];
    __shared__ float sW[32][132];
    const int t = threadIdx.x, i0 = blockIdx.x * 64;
    const int rb = (t >> 5) * 8, cb = (t & 31) * 4;
    float acc[8][4];
#pragma unroll
    for (int r = 0; r < 8; r++)
#pragma unroll
        for (int c = 0; c < 4; c++) acc[r][c] = 0.f;
    for (int k0 = 0; k0 < FIN; k0 += 32) {
        __syncthreads();
#pragma unroll
        for (int it = 0; it < 2; it++) {
            int idx = t + 256 * it, row = idx >> 3, kc = (idx & 7) * 4;
            float4 v = *reinterpret_cast<const float4*>(h + (size_t)(i0 + row) * FIN + k0 + kc);
            sH[kc][row] = v.x; sH[kc + 1][row] = v.y; sH[kc + 2][row] = v.z; sH[kc + 3][row] = v.w;
        }
#pragma unroll
        for (int it = 0; it < 4; it++) {
            int idx = t + 256 * it, f = idx >> 3, kc = (idx & 7) * 4;
            float4 v = *reinterpret_cast<const float4*>(W + (size_t)f * FIN + k0 + kc);
            sW[kc][f] = v.x; sW[kc + 1][f] = v.y; sW[kc + 2][f] = v.z; sW[kc + 3][f] = v.w;
        }
        __syncthreads();
#pragma unroll
        for (int k = 0; k < 32; k++) {
            float a[8], b[4];
            *reinterpret_cast<float4*>(a)     = *reinterpret_cast<const float4*>(&sH[k][rb]);
            *reinterpret_cast<float4*>(a + 4) = *reinterpret_cast<const float4*>(&sH[k][rb + 4]);
            *reinterpret_cast<float4*>(b)     = *reinterpret_cast<const float4*>(&sW[k][cb]);
#pragma unroll
            for (int r = 0; r < 8; r++)
#pragma unroll
                for (int c = 0; c < 4; c++) acc[r][c] = fmaf(a[r], b[c], acc[r][c]);
        }
    }
#pragma unroll
    for (int r = 0; r < 8; r++)
        *reinterpret_cast<float4*>(g_Wh + (size_t)(i0 + rb + r) * FOUT + cb) =
            make_float4(acc[r][0], acc[r][1], acc[r][2], acc[r][3]);
#pragma unroll
    for (int c = 0; c < 4; c++) {
        uint4 v;
        v.x = packh2(acc[0][c], acc[1][c]);
        v.y = packh2(acc[2][c], acc[3][c]);
        v.z = packh2(acc[4][c], acc[5][c]);
        v.w = packh2(acc[6][c], acc[7][c]);
        *reinterpret_cast<uint4*>(g_WhT + (size_t)(cb + c) * NN + i0 + rb) = v;
    }
}

// ---------------- Phase 2: raw scores ----------------
__global__ void __launch_bounds__(256) k_score(const float* __restrict__ a_vec) {
    int gw = (blockIdx.x * blockDim.x + threadIdx.x) >> 5, lane = threadIdx.x & 31;
    if (gw >= NN) return;
    float4 w  = reinterpret_cast<const float4*>(g_Wh + (size_t)gw * FOUT)[lane];
    float4 as = reinterpret_cast<const float4*>(a_vec)[lane];
    float4 ad = reinterpret_cast<const float4*>(a_vec + FOUT)[lane];
    float ss = w.x * as.x + w.y * as.y + w.z * as.z + w.w * as.w;
    float sd = w.x * ad.x + w.y * ad.y + w.z * ad.z + w.w * ad.w;
#pragma unroll
    for (int o = 16; o > 0; o >>= 1) {
        ss += __shfl_xor_sync(0xffffffffu, ss, o);
        sd += __shfl_xor_sync(0xffffffffu, sd, o);
    }
    if (lane == 0) { g_ss[gw] = ss; g_sd[gw] = sd; }
}

// ---------------- Phase 2b: max(sd); prescaled exp factors ----------------
__global__ void __launch_bounds__(256) k_max() {
    __shared__ float sm[8];
    const int t = threadIdx.x;
    float m = -1e30f;
    for (int i = t; i < NN; i += 256) m = fmaxf(m, g_sd[i]);
#pragma unroll
    for (int o = 16; o > 0; o >>= 1) m = fmaxf(m, __shfl_xor_sync(0xffffffffu, m, o));
    if ((t & 31) == 0) sm[t >> 5] = m;
    __syncthreads();
    if (t == 0) {
        float r = sm[0];
#pragma unroll
        for (int i = 1; i < 8; i++) r = fmaxf(r, sm[i]);
        g_M = r;
    }
}

__global__ void __launch_bounds__(256) k_prep() {
    int i = blockIdx.x * 256 + threadIdx.x;
    float M = g_M;
    float ss = g_ss[i], sd = g_sd[i];
    float x = ss + M;
    float LRm = x > 0.f ? x : 0.2f * x;   // exact upper bound of LR(ss + sd_j)
    g_us[i] = expf(ss - LRm);
    g_u5[i] = expf(fmaf(0.2f, ss, -LRm));
    g_vd[i] = expf(sd);
    g_v5[i] = expf(0.2f * sd);
}

// ------- Phase 3: fused masked-softmax @ Wh (fp16 scalar-LDS mma) -------
extern __shared__ float dynsmem[];

__global__ void __launch_bounds__(256, 1) k_gat(const int* __restrict__ adj,
                                                float* __restrict__ out) {
    // sA: 64 x SPH halves = 17408 B ; sB: 2 x (128 x SBH halves) = 69632 B ; sDen 256 B
    char* base = reinterpret_cast<char*>(dynsmem);
    const uint32_t sAu  = (uint32_t)__cvta_generic_to_shared(base);
    const uint32_t sBu0 = sAu + 17408u;
    float* sDen = reinterpret_cast<float*>(base + 87040);

    const int t    = threadIdx.x;
    const int lane = t & 31;
    const int w    = t >> 5;
    const int i0   = blockIdx.x * MT;
    const int jl   = lane * 4;

    // ---- P-gen row constants (rows w + 8*it) ----
    float ssr[8], usr[8], u5r[8], den[8];
#pragma unroll
    for (int it = 0; it < 8; it++) {
        int gr = i0 + w + 8 * it;
        ssr[it] = g_ss[gr]; usr[it] = g_us[gr]; u5r[it] = g_u5[gr];
        den[it] = 0.f;
    }

    // ---- MMA mapping: warp grid 2(rows) x 4(cols), 32x32 tiles ----
    const int mrow = (w & 1) * 32;
    const int ncol = (w >> 1) * 32;
    const int qr   = lane >> 2;
    const int qc   = lane & 3;
    const uint32_t aB = sAu + (uint32_t)((mrow + qr) * SPH + 2 * qc) * 2u;
    const uint32_t bB = (uint32_t)((ncol + qr) * SBH + 2 * qc) * 2u;

    float acc[2][4][4];
#pragma unroll
    for (int mb = 0; mb < 2; mb++)
#pragma unroll
        for (int nb = 0; nb < 4; nb++)
#pragma unroll
            for (int c = 0; c < 4; c++) acc[mb][nb][c] = 0.f;

    // ---- prologue: B(0) cp.async + tile-0 reg prefetch ----
#pragma unroll
    for (int i = 0; i < 8; i++) {
        int g = t + 256 * i, n = g >> 4, c = g & 15;
        CPASYNC16(sBu0 + (uint32_t)(n * SBH * 2 + c * 16),
                  g_WhT + (size_t)n * NN + c * 8);
    }
    CPCOMMIT();
    int4   amC[8];
    float4 sdC = *reinterpret_cast<const float4*>(g_sd + jl);
    float4 vdC = *reinterpret_cast<const float4*>(g_vd + jl);
    float4 v5C = *reinterpret_cast<const float4*>(g_v5 + jl);
#pragma unroll
    for (int it = 0; it < 8; it++)
        amC[it] = *reinterpret_cast<const int4*>(adj + (size_t)(i0 + w + 8 * it) * NN + jl);

    for (int jt = 0; jt < NTL; jt++) {
        const int s = jt & 1;

        // ---- P-gen(jt): rows w+8it, cols jl..jl+3 -> sA (fp16) ----
#pragma unroll
        for (int it = 0; it < 8; it++) {
            int r = w + 8 * it;
            float p0 = (ssr[it] + sdC.x) > 0.f ? usr[it] * vdC.x : u5r[it] * v5C.x;
            float p1 = (ssr[it] + sdC.y) > 0.f ? usr[it] * vdC.y : u5r[it] * v5C.y;
            float p2 = (ssr[it] + sdC.z) > 0.f ? usr[it] * vdC.z : u5r[it] * v5C.z;
            float p3 = (ssr[it] + sdC.w) > 0.f ? usr[it] * vdC.w : u5r[it] * v5C.w;
            p0 = amC[it].x > 0 ? p0 : 0.f;
            p1 = amC[it].y > 0 ? p1 : 0.f;
            p2 = amC[it].z > 0 ? p2 : 0.f;
            p3 = amC[it].w > 0 ? p3 : 0.f;
            den[it] += (p0 + p1) + (p2 + p3);
            STS64(sAu + (uint32_t)(r * SPH + jl) * 2u, packh2(p0, p1), packh2(p2, p3));
        }

        // ---- issue B(jt+1) cp.async; prefetch regs(jt+1) ----
        if (jt + 1 < NTL) {
            const __half* bsrc = g_WhT + (size_t)(jt + 1) * JT;
            const uint32_t d = sBu0 + (uint32_t)((s ^ 1) * 34816);
#pragma unroll
            for (int i = 0; i < 8; i++) {
                int g = t + 256 * i, n = g >> 4, c = g & 15;
                CPASYNC16(d + (uint32_t)(n * SBH * 2 + c * 16),
                          bsrc + (size_t)n * NN + c * 8);
            }
        }
        CPCOMMIT();
        if (jt + 1 < NTL) {
            const int j0n = (jt + 1) * JT;
            sdC = *reinterpret_cast<const float4*>(g_sd + j0n + jl);
            vdC = *reinterpret_cast<const float4*>(g_vd + j0n + jl);
            v5C = *reinterpret_cast<const float4*>(g_v5 + j0n + jl);
#pragma unroll
            for (int it = 0; it < 8; it++)
                amC[it] = *reinterpret_cast<const int4*>(adj + (size_t)(i0 + w + 8 * it) * NN + j0n + jl);
        }

        CPWAIT1();           // B(jt) resident
        __syncthreads();     // sA(jt) published

        // ---- MMA(jt): all scalar LDS.32, conflict-free ----
        const uint32_t bBs = sBu0 + (uint32_t)(s * 34816) + bB;
#pragma unroll
        for (int ks = 0; ks < 8; ks++) {
            const uint32_t ko = (uint32_t)(ks * 32);
            unsigned a[2][4], b0[4], b1[4];
#pragma unroll
            for (int mb = 0; mb < 2; mb++) {
                const uint32_t ab = aB + (uint32_t)(mb * 16 * SPH * 2) + ko;
                LDS32(a[mb][0], ab);
                LDS32(a[mb][1], ab + 8u * SPH * 2u);
                LDS32(a[mb][2], ab + 16u);
                LDS32(a[mb][3], ab + 8u * SPH * 2u + 16u);
            }
#pragma unroll
            for (int nb = 0; nb < 4; nb++) {
                const uint32_t bb = bBs + (uint32_t)(nb * 8 * SBH * 2) + ko;
                LDS32(b0[nb], bb);
                LDS32(b1[nb], bb + 16u);
            }
#pragma unroll
            for (int mb = 0; mb < 2; mb++)
#pragma unroll
                for (int nb = 0; nb < 4; nb++)
                    MMA16(acc[mb][nb], a[mb][0], a[mb][1], a[mb][2], a[mb][3],
                          b0[nb], b1[nb]);
        }
        __syncthreads();     // sA free for P-gen(jt+1)
    }

    // ---- denominators ----
#pragma unroll
    for (int it = 0; it < 8; it++) {
        float d = den[it];
#pragma unroll
        for (int o = 16; o > 0; o >>= 1) d += __shfl_xor_sync(0xffffffffu, d, o);
        if (lane == 0) sDen[w + 8 * it] = d;
    }
    __syncthreads();

    // ---- epilogue: scale + store ----
#pragma unroll
    for (int mb = 0; mb < 2; mb++) {
        const int rbase = mrow + mb * 16 + qr;
        const float rd0 = 1.f / sDen[rbase];
        const float rd1 = 1.f / sDen[rbase + 8];
        const int r0 = i0 + rbase;
#pragma unroll
        for (int nb = 0; nb < 4; nb++) {
            int col = ncol + nb * 8 + qc * 2;
            *reinterpret_cast<float2*>(out + (size_t)r0 * FOUT + col) =
                make_float2(acc[mb][nb][0] * rd0, acc[mb][nb][1] * rd0);
            *reinterpret_cast<float2*>(out + (size_t)(r0 + 8) * FOUT + col) =
                make_float2(acc[mb][nb][2] * rd1, acc[mb][nb][3] * rd1);
        }
    }
}

// ---------------------------------------------------------------
extern "C" void kernel_launch(void* const* d_in, const int* in_sizes, int n_in,
                              void* d_out, int out_size) {
    const float* h   = (const float*)d_in[0];
    const int*   adj = (const int*)d_in[1];
    const float* W   = (const float*)d_in[2];
    const float* a   = (const float*)d_in[3];
    float*       out = (float*)d_out;
    (void)in_sizes; (void)n_in; (void)out_size;

    const int smem_bytes = 17408 + 69632 + 256;   // 87296
    static int inited = 0;
    if (!inited) {
        cudaFuncSetAttribute(k_gat, cudaFuncAttributeMaxDynamicSharedMemorySize, smem_bytes);
        inited = 1;
    }
    k_wh<<<NN / 64, 256>>>(h, W);
    k_score<<<NN / 8, 256>>>(a);
    k_max<<<1, 256>>>();
    k_prep<<<NN / 256, 256>>>();
    k_gat<<<NN / MT, 256, smem_bytes>>>(adj, out);
}

// round 10
// speedup vs baseline: 2.8946x; 1.3168x over previous
#include <cuda_runtime.h>
#include <cuda_fp16.h>
#include <cstdint>
#include <cstddef>

#define NN   8192
#define FIN  256
#define FOUT 128
#define MT   64
#define JT   128
#define NT2  32     // tiles per CTA (half of j-range)
#define SPH  136
#define SBH  136

__device__ float  g_Wh[NN * FOUT];
__device__ __half g_WhT[FOUT * NN];
__device__ float  g_ss[NN], g_sd[NN];
__device__ float  g_us[NN], g_u5[NN];
__device__ float  g_vd[NN], g_v5[NN];
__device__ float  g_M;
__device__ float  g_pnum[2 * NN * FOUT];   // split-J partial numerators
__device__ float  g_pden[2 * NN];

#define CPASYNC16(dst, src) \
    asm volatile("cp.async.cg.shared.global [%0], [%1], 16;" :: "r"(dst), "l"(src))
#define CPCOMMIT() asm volatile("cp.async.commit_group;" ::: "memory")
#define CPWAIT1()  asm volatile("cp.async.wait_group 1;" ::: "memory")
#define LDS32(x, a) asm volatile("ld.shared.b32 %0, [%1];" : "=r"(x) : "r"(a))
#define STS64(a, x, y) \
    asm volatile("st.shared.v2.b32 [%0], {%1,%2};" :: "r"(a), "r"(x), "r"(y) : "memory")
#define MMA16(d, a0, a1, a2, a3, b0, b1) \
    asm volatile("mma.sync.aligned.m16n8k16.row.col.f32.f16.f16.f32 " \
                 "{%0,%1,%2,%3}, {%4,%5,%6,%7}, {%8,%9}, {%0,%1,%2,%3};\n" \
                 : "+f"(d[0]), "+f"(d[1]), "+f"(d[2]), "+f"(d[3]) \
                 : "r"(a0), "r"(a1), "r"(a2), "r"(a3), "r"(b0), "r"(b1))

__device__ __forceinline__ unsigned packh2(float a, float b) {
    __half2 h = __floats2half2_rn(a, b);
    return *reinterpret_cast<unsigned*>(&h);
}

// ---------------- Phase 1: Wh = h @ W^T (32 rows/CTA, occ 2) ----------------
__global__ void __launch_bounds__(256, 2) k_wh(const float* __restrict__ h,
                                               const float* __restrict__ W) {
    __shared__ float sH[32][36];
    __shared__ float sW[32][132];
    const int t = threadIdx.x, i0 = blockIdx.x * 32;
    const int rb = (t >> 5) * 4, cb = (t & 31) * 4;
    float acc[4][4];
#pragma unroll
    for (int r = 0; r < 4; r++)
#pragma unroll
        for (int c = 0; c < 4; c++) acc[r][c] = 0.f;
    for (int k0 = 0; k0 < FIN; k0 += 32) {
        __syncthreads();
        {
            int row = t >> 3, kc = (t & 7) * 4;
            float4 v = *reinterpret_cast<const float4*>(h + (size_t)(i0 + row) * FIN + k0 + kc);
            sH[kc][row] = v.x; sH[kc + 1][row] = v.y; sH[kc + 2][row] = v.z; sH[kc + 3][row] = v.w;
        }
#pragma unroll
        for (int it = 0; it < 4; it++) {
            int idx = t + 256 * it, f = idx >> 3, kc = (idx & 7) * 4;
            float4 v = *reinterpret_cast<const float4*>(W + (size_t)f * FIN + k0 + kc);
            sW[kc][f] = v.x; sW[kc + 1][f] = v.y; sW[kc + 2][f] = v.z; sW[kc + 3][f] = v.w;
        }
        __syncthreads();
#pragma unroll
        for (int k = 0; k < 32; k++) {
            float a[4], b[4];
            *reinterpret_cast<float4*>(a) = *reinterpret_cast<const float4*>(&sH[k][rb]);
            *reinterpret_cast<float4*>(b) = *reinterpret_cast<const float4*>(&sW[k][cb]);
#pragma unroll
            for (int r = 0; r < 4; r++)
#pragma unroll
                for (int c = 0; c < 4; c++) acc[r][c] = fmaf(a[r], b[c], acc[r][c]);
        }
    }
#pragma unroll
    for (int r = 0; r < 4; r++)
        *reinterpret_cast<float4*>(g_Wh + (size_t)(i0 + rb + r) * FOUT + cb) =
            make_float4(acc[r][0], acc[r][1], acc[r][2], acc[r][3]);
#pragma unroll
    for (int c = 0; c < 4; c++) {
        uint2 v;
        v.x = packh2(acc[0][c], acc[1][c]);
        v.y = packh2(acc[2][c], acc[3][c]);
        *reinterpret_cast<uint2*>(g_WhT + (size_t)(cb + c) * NN + i0 + rb) = v;
    }
}

// ---------------- Phase 2: raw scores ----------------
__global__ void __launch_bounds__(256) k_score(const float* __restrict__ a_vec) {
    int gw = (blockIdx.x * blockDim.x + threadIdx.x) >> 5, lane = threadIdx.x & 31;
    if (gw >= NN) return;
    float4 w  = reinterpret_cast<const float4*>(g_Wh + (size_t)gw * FOUT)[lane];
    float4 as = reinterpret_cast<const float4*>(a_vec)[lane];
    float4 ad = reinterpret_cast<const float4*>(a_vec + FOUT)[lane];
    float ss = w.x * as.x + w.y * as.y + w.z * as.z + w.w * as.w;
    float sd = w.x * ad.x + w.y * ad.y + w.z * ad.z + w.w * ad.w;
#pragma unroll
    for (int o = 16; o > 0; o >>= 1) {
        ss += __shfl_xor_sync(0xffffffffu, ss, o);
        sd += __shfl_xor_sync(0xffffffffu, sd, o);
    }
    if (lane == 0) { g_ss[gw] = ss; g_sd[gw] = sd; }
}

// ---------------- Phase 2b: max(sd); prescaled exp factors ----------------
__global__ void __launch_bounds__(256) k_max() {
    __shared__ float sm[8];
    const int t = threadIdx.x;
    float m = -1e30f;
    for (int i = t; i < NN; i += 256) m = fmaxf(m, g_sd[i]);
#pragma unroll
    for (int o = 16; o > 0; o >>= 1) m = fmaxf(m, __shfl_xor_sync(0xffffffffu, m, o));
    if ((t & 31) == 0) sm[t >> 5] = m;
    __syncthreads();
    if (t == 0) {
        float r = sm[0];
#pragma unroll
        for (int i = 1; i < 8; i++) r = fmaxf(r, sm[i]);
        g_M = r;
    }
}

__global__ void __launch_bounds__(256) k_prep() {
    int i = blockIdx.x * 256 + threadIdx.x;
    float M = g_M;
    float ss = g_ss[i], sd = g_sd[i];
    float x = ss + M;
    float LRm = x > 0.f ? x : 0.2f * x;
    g_us[i] = expf(ss - LRm);
    g_u5[i] = expf(fmaf(0.2f, ss, -LRm));
    g_vd[i] = expf(sd);
    g_v5[i] = expf(0.2f * sd);
}

// ------- Phase 3: fused masked-softmax numerator (split-J, occ 2) -------
extern __shared__ float dynsmem[];

__global__ void __launch_bounds__(256, 2) k_gat(const int* __restrict__ adj) {
    char* base = reinterpret_cast<char*>(dynsmem);
    const uint32_t sAu  = (uint32_t)__cvta_generic_to_shared(base);
    const uint32_t sBu0 = sAu + 17408u;
    float* sDen = reinterpret_cast<float*>(base + 87040);

    const int t    = threadIdx.x;
    const int lane = t & 31;
    const int w    = t >> 5;
    const int i0    = (blockIdx.x >> 1) * MT;
    const int halfj = blockIdx.x & 1;
    const int jbase = halfj * (NN / 2);
    const int jl    = lane * 4;

    // P-gen row constants (rows w + 8*it)
    float ssr[8], usr[8], u5r[8], den[8];
#pragma unroll
    for (int it = 0; it < 8; it++) {
        int gr = i0 + w + 8 * it;
        ssr[it] = g_ss[gr]; usr[it] = g_us[gr]; u5r[it] = g_u5[gr];
        den[it] = 0.f;
    }

    const int mrow = (w & 1) * 32;
    const int ncol = (w >> 1) * 32;
    const int qr   = lane >> 2;
    const int qc   = lane & 3;
    const uint32_t aB = sAu + (uint32_t)((mrow + qr) * SPH + 2 * qc) * 2u;
    const uint32_t bB = (uint32_t)((ncol + qr) * SBH + 2 * qc) * 2u;

    float acc[2][4][4];
#pragma unroll
    for (int mb = 0; mb < 2; mb++)
#pragma unroll
        for (int nb = 0; nb < 4; nb++)
#pragma unroll
            for (int c = 0; c < 4; c++) acc[mb][nb][c] = 0.f;

    // ---- prologue: B(0) cp.async + tile-0 reg prefetch ----
#pragma unroll
    for (int i = 0; i < 8; i++) {
        int g = t + 256 * i, n = g >> 4, c = g & 15;
        CPASYNC16(sBu0 + (uint32_t)(n * SBH * 2 + c * 16),
                  g_WhT + (size_t)n * NN + jbase + c * 8);
    }
    CPCOMMIT();
    float4 sdC = *reinterpret_cast<const float4*>(g_sd + jbase + jl);
    float4 vdC = *reinterpret_cast<const float4*>(g_vd + jbase + jl);
    float4 v5C = *reinterpret_cast<const float4*>(g_v5 + jbase + jl);
    unsigned mcur = 0;
#pragma unroll
    for (int it = 0; it < 8; it++) {
        int4 am = *reinterpret_cast<const int4*>(adj + (size_t)(i0 + w + 8 * it) * NN + jbase + jl);
        unsigned b = (am.x > 0 ? 1u : 0u) | (am.y > 0 ? 2u : 0u)
                   | (am.z > 0 ? 4u : 0u) | (am.w > 0 ? 8u : 0u);
        mcur |= b << (4 * it);
    }

    for (int jt = 0; jt < NT2; jt++) {
        const int s = jt & 1;

        // ---- P-gen(jt) -> sA (fp16) ----
#pragma unroll
        for (int it = 0; it < 8; it++) {
            int r = w + 8 * it;
            unsigned mk = mcur >> (4 * it);
            float p0 = (ssr[it] + sdC.x) > 0.f ? usr[it] * vdC.x : u5r[it] * v5C.x;
            float p1 = (ssr[it] + sdC.y) > 0.f ? usr[it] * vdC.y : u5r[it] * v5C.y;
            float p2 = (ssr[it] + sdC.z) > 0.f ? usr[it] * vdC.z : u5r[it] * v5C.z;
            float p3 = (ssr[it] + sdC.w) > 0.f ? usr[it] * vdC.w : u5r[it] * v5C.w;
            p0 = (mk & 1u) ? p0 : 0.f;
            p1 = (mk & 2u) ? p1 : 0.f;
            p2 = (mk & 4u) ? p2 : 0.f;
            p3 = (mk & 8u) ? p3 : 0.f;
            den[it] += (p0 + p1) + (p2 + p3);
            STS64(sAu + (uint32_t)(r * SPH + jl) * 2u, packh2(p0, p1), packh2(p2, p3));
        }

        // ---- issue B(jt+1) cp.async; prefetch regs(jt+1) ----
        if (jt + 1 < NT2) {
            const int j0n = jbase + (jt + 1) * JT;
            const __half* bsrc = g_WhT + j0n;
            const uint32_t d = sBu0 + (uint32_t)((s ^ 1) * 34816);
#pragma unroll
            for (int i = 0; i < 8; i++) {
                int g = t + 256 * i, n = g >> 4, c = g & 15;
                CPASYNC16(d + (uint32_t)(n * SBH * 2 + c * 16),
                          bsrc + (size_t)n * NN + c * 8);
            }
            CPCOMMIT();
            sdC = *reinterpret_cast<const float4*>(g_sd + j0n + jl);
            vdC = *reinterpret_cast<const float4*>(g_vd + j0n + jl);
            v5C = *reinterpret_cast<const float4*>(g_v5 + j0n + jl);
            unsigned mn = 0;
#pragma unroll
            for (int it = 0; it < 8; it++) {
                int4 am = *reinterpret_cast<const int4*>(
                    adj + (size_t)(i0 + w + 8 * it) * NN + j0n + jl);
                unsigned b = (am.x > 0 ? 1u : 0u) | (am.y > 0 ? 2u : 0u)
                           | (am.z > 0 ? 4u : 0u) | (am.w > 0 ? 8u : 0u);
                mn |= b << (4 * it);
            }
            mcur = mn;
        } else {
            CPCOMMIT();
        }

        CPWAIT1();
        __syncthreads();

        // ---- MMA(jt) ----
        const uint32_t bBs = sBu0 + (uint32_t)(s * 34816) + bB;
#pragma unroll
        for (int ks = 0; ks < 8; ks++) {
            const uint32_t ko = (uint32_t)(ks * 32);
            unsigned a[2][4], b0[4], b1[4];
#pragma unroll
            for (int mb = 0; mb < 2; mb++) {
                const uint32_t ab = aB + (uint32_t)(mb * 16 * SPH * 2) + ko;
                LDS32(a[mb][0], ab);
                LDS32(a[mb][1], ab + 8u * SPH * 2u);
                LDS32(a[mb][2], ab + 16u);
                LDS32(a[mb][3], ab + 8u * SPH * 2u + 16u);
            }
#pragma unroll
            for (int nb = 0; nb < 4; nb++) {
                const uint32_t bb = bBs + (uint32_t)(nb * 8 * SBH * 2) + ko;
                LDS32(b0[nb], bb);
                LDS32(b1[nb], bb + 16u);
            }
#pragma unroll
            for (int mb = 0; mb < 2; mb++)
#pragma unroll
                for (int nb = 0; nb < 4; nb++)
                    MMA16(acc[mb][nb], a[mb][0], a[mb][1], a[mb][2], a[mb][3],
                          b0[nb], b1[nb]);
        }
        __syncthreads();
    }

    // ---- partial denominators ----
#pragma unroll
    for (int it = 0; it < 8; it++) {
        float d = den[it];
#pragma unroll
        for (int o = 16; o > 0; o >>= 1) d += __shfl_xor_sync(0xffffffffu, d, o);
        if (lane == 0) sDen[w + 8 * it] = d;
    }
    __syncthreads();

    // ---- store partial numerators + denominators ----
    if (t < MT) g_pden[(size_t)halfj * NN + i0 + t] = sDen[t];
    float* pn = g_pnum + (size_t)halfj * NN * FOUT;
#pragma unroll
    for (int mb = 0; mb < 2; mb++) {
        const int rbase = mrow + mb * 16 + qr;
        const int r0 = i0 + rbase;
#pragma unroll
        for (int nb = 0; nb < 4; nb++) {
            int col = ncol + nb * 8 + qc * 2;
            *reinterpret_cast<float2*>(pn + (size_t)r0 * FOUT + col) =
                make_float2(acc[mb][nb][0], acc[mb][nb][1]);
            *reinterpret_cast<float2*>(pn + (size_t)(r0 + 8) * FOUT + col) =
                make_float2(acc[mb][nb][2], acc[mb][nb][3]);
        }
    }
}

// ---------------- Phase 4: combine split-J partials ----------------
__global__ void __launch_bounds__(256) k_combine(float* __restrict__ out) {
    int idx = blockIdx.x * 256 + threadIdx.x;
#pragma unroll
    for (int it = 0; it < 8; it++, idx += 32768) {
        int i = idx >> 5;
        float4 a = reinterpret_cast<const float4*>(g_pnum)[idx];
        float4 b = reinterpret_cast<const float4*>(g_pnum + (size_t)NN * FOUT)[idx];
        float rd = 1.f / (g_pden[i] + g_pden[NN + i]);
        reinterpret_cast<float4*>(out)[idx] = make_float4(
            (a.x + b.x) * rd, (a.y + b.y) * rd, (a.z + b.z) * rd, (a.w + b.w) * rd);
    }
}

// ---------------------------------------------------------------
extern "C" void kernel_launch(void* const* d_in, const int* in_sizes, int n_in,
                              void* d_out, int out_size) {
    const float* h   = (const float*)d_in[0];
    const int*   adj = (const int*)d_in[1];
    const float* W   = (const float*)d_in[2];
    const float* a   = (const float*)d_in[3];
    float*       out = (float*)d_out;
    (void)in_sizes; (void)n_in; (void)out_size;

    const int smem_bytes = 17408 + 69632 + 256;   // 87296
    static int inited = 0;
    if (!inited) {
        cudaFuncSetAttribute(k_gat, cudaFuncAttributeMaxDynamicSharedMemorySize, smem_bytes);
        inited = 1;
    }
    k_wh<<<NN / 32, 256>>>(h, W);
    k_score<<<NN / 8, 256>>>(a);
    k_max<<<1, 256>>>();
    k_prep<<<NN / 256, 256>>>();
    k_gat<<<2 * (NN / MT), 256, smem_bytes>>>(adj);
    k_combine<<<128, 256>>>(out);
}